// round 9
// baseline (speedup 1.0000x reference)
#include <cuda_runtime.h>
#include <cuda_fp16.h>
#include <math.h>

#define N_NODES 100000
#define N_EDGES 3200000
#define SCAN_B  512
#define SCAN_NBLK ((N_NODES + SCAN_B - 1) / SCAN_B)   // 196
#define FULLM 0xffffffffu
#define TB 256
#define EB ((N_EDGES + TB - 1) / TB)                  // fill blocks
#define GB ((N_NODES * 64 + TB - 1) / TB)             // gemm1 blocks

// ---------------- device scratch ----------------------------------------------
__device__ int    g_is64;
__device__ int    g_cnt[N_NODES];
__device__ int    g_rowptr[N_NODES + 1];
__device__ int    g_cursor[N_NODES];
__device__ int    g_srcs[N_EDGES];
__device__ unsigned long long g_scan_pack[SCAN_NBLK]; // (value<<2)|flag: 1=agg,2=incl
__device__ float  g_dinv[N_NODES];
__device__ __half g_H1[N_NODES * 64];   // layer-1 gather buf (128B rows)
__device__ __half g_H2[N_NODES * 32];   // layer-2 gather buf (64B rows)
__device__ __half g_H3[N_NODES * 16];   // layer-3 gather buf (32B rows)
__device__ float  g_H4[N_NODES * 8];    // layer-4 gather buf (32B rows, fp32)

// ---------------- init: zero cnt + scan state + dtype detect --------------------
__global__ __launch_bounds__(TB) void k_init(const void* ei) {
    int i = blockIdx.x * blockDim.x + threadIdx.x;
    if (i < N_NODES) g_cnt[i] = 0;
    if (blockIdx.x == 0) {
        __shared__ int any_nz;
        if (threadIdx.x == 0) any_nz = 0;
        __syncthreads();
        const int* w = (const int*)ei;
        for (int k = threadIdx.x; k < 4096; k += blockDim.x)
            if (w[2 * k + 1] != 0) any_nz = 1;
        __syncthreads();
        if (threadIdx.x == 0) g_is64 = any_nz ? 0 : 1;
    }
    if (blockIdx.x == 1 && threadIdx.x < SCAN_NBLK)
        g_scan_pack[threadIdx.x] = 0ull;
}

// ---------------- CSR count -----------------------------------------------------
__global__ void k_count(const void* __restrict__ ei) {
    int e = blockIdx.x * blockDim.x + threadIdx.x;
    if (e < N_EDGES) {
        int d = g_is64 ? (int)((const long long*)ei)[(long long)N_EDGES + e]
                       : ((const int*)ei)[N_EDGES + e];
        if ((unsigned)d < N_NODES) atomicAdd(&g_cnt[d], 1);
    }
}

// ---------------- single-pass scan (decoupled lookback) + finalize ---------------
__global__ __launch_bounds__(SCAN_B) void k_scan() {
    __shared__ int wsum[SCAN_B / 32];
    __shared__ int s_total;
    __shared__ int s_base;
    int tid  = threadIdx.x;
    int lane = tid & 31;
    int wid  = tid >> 5;
    int b    = blockIdx.x;
    int idx  = b * SCAN_B + tid;
    int v = (idx < N_NODES) ? g_cnt[idx] : 0;

    int incl = v;
#pragma unroll
    for (int off = 1; off < 32; off <<= 1) {
        int t = __shfl_up_sync(FULLM, incl, off);
        if (lane >= off) incl += t;
    }
    if (lane == 31) wsum[wid] = incl;
    __syncthreads();
    if (wid == 0) {
        int ws = (lane < SCAN_B / 32) ? wsum[lane] : 0;
#pragma unroll
        for (int off = 1; off < SCAN_B / 32; off <<= 1) {
            int t = __shfl_up_sync(FULLM, ws, off);
            if (lane >= off) ws += t;
        }
        if (lane < SCAN_B / 32) wsum[lane] = ws;
    }
    __syncthreads();
    int base = (wid > 0) ? wsum[wid - 1] : 0;
    int excl = base + incl - v;
    if (tid == SCAN_B - 1) s_total = base + incl;
    __syncthreads();

    // decoupled lookback (all 196 blocks co-resident -> no deadlock)
    if (tid == 0) {
        int total = s_total;
        if (b == 0) {
            atomicExch(&g_scan_pack[0], ((unsigned long long)total << 2) | 2ull);
            s_base = 0;
        } else {
            atomicExch(&g_scan_pack[b], ((unsigned long long)total << 2) | 1ull);
            int run = 0;
            int i = b - 1;
            while (true) {
                unsigned long long p;
                do { p = atomicAdd(&g_scan_pack[i], 0ull); } while ((p & 3ull) == 0ull);
                run += (int)(p >> 2);
                if ((p & 3ull) == 2ull) break;
                i--;
            }
            atomicExch(&g_scan_pack[b],
                       ((unsigned long long)(run + total) << 2) | 2ull);
            s_base = run;
        }
    }
    __syncthreads();

    if (idx < N_NODES) {
        int rp = s_base + excl;
        g_rowptr[idx] = rp;
        g_cursor[idx] = rp;
        g_dinv[idx]   = rsqrtf((float)v + 1.0f);   // +1 self loop
    }
    if (b == SCAN_NBLK - 1 && tid == 0)
        g_rowptr[N_NODES] = s_base + s_total;
}

// ---------------- fused: CSR fill + layer-1 GEMM (co-scheduled) ------------------
__global__ __launch_bounds__(TB) void k_fill_gemm1(
    const void* __restrict__ ei, const float* __restrict__ x,
    const float* __restrict__ W)
{
    __shared__ float sW[34 * 64];
    if (blockIdx.x < EB) {
        int e = blockIdx.x * TB + threadIdx.x;
        if (e < N_EDGES) {
            int is64 = g_is64;
            int s, d;
            if (is64) {
                s = (int)((const long long*)ei)[e];
                d = (int)((const long long*)ei)[(long long)N_EDGES + e];
            } else {
                s = ((const int*)ei)[e];
                d = ((const int*)ei)[N_EDGES + e];
            }
            if ((unsigned)d < N_NODES) {
                int p = atomicAdd(&g_cursor[d], 1);
                g_srcs[p] = s;
            }
        }
    } else {
        for (int i = threadIdx.x; i < 34 * 64; i += blockDim.x) sW[i] = W[i];
        __syncthreads();
        int idx = (blockIdx.x - EB) * TB + threadIdx.x;
        int node = idx >> 6;
        int f    = idx & 63;
        if (node >= N_NODES) return;
        const float* hr = x + (size_t)node * 34;
        float acc = 0.f;
#pragma unroll
        for (int k = 0; k < 34; k++) acc += hr[k] * sW[k * 64 + f];
        g_H1[(size_t)node * 64 + f] = __float2half(acc * g_dinv[node]);
    }
}

// ---------------- F1: aggregate 64d + tanh + GEMM 64->32 -> H2 ------------------
__global__ __launch_bounds__(256) void k_f1(
    const float* __restrict__ b1, const float* __restrict__ W2)
{
    __shared__ float sW[64 * 32];   // 8KB
    for (int i = threadIdx.x; i < 64 * 32; i += blockDim.x) sW[i] = W2[i];
    __syncthreads();

    int warp = (blockIdx.x * blockDim.x + threadIdx.x) >> 5;
    int lane = threadIdx.x & 31;
    if (warp >= N_NODES) return;
    const int node = warp;
    const __half2* t = (const __half2*)g_H1;

    float2 self = __half22float2(t[(size_t)node * 32 + lane]);
    float ax0 = self.x, ay0 = self.y, ax1 = 0.f, ay1 = 0.f;

    int start = g_rowptr[node];
    int end   = g_rowptr[node + 1];
    int e0 = start;
    for (; e0 + 32 <= end; e0 += 32) {
        int s = g_srcs[e0 + lane];
#pragma unroll
        for (int j = 0; j < 32; j += 4) {      // 4 loads in flight
            int s0 = __shfl_sync(FULLM, s, j);
            int s1 = __shfl_sync(FULLM, s, j + 1);
            int s2 = __shfl_sync(FULLM, s, j + 2);
            int s3 = __shfl_sync(FULLM, s, j + 3);
            float2 r0 = __half22float2(t[(size_t)s0 * 32 + lane]);
            float2 r1 = __half22float2(t[(size_t)s1 * 32 + lane]);
            float2 r2 = __half22float2(t[(size_t)s2 * 32 + lane]);
            float2 r3 = __half22float2(t[(size_t)s3 * 32 + lane]);
            ax0 += r0.x; ay0 += r0.y;
            ax1 += r1.x; ay1 += r1.y;
            ax0 += r2.x; ay0 += r2.y;
            ax1 += r3.x; ay1 += r3.y;
        }
    }
    if (e0 < end) {
        int m = end - e0;
        int s = (e0 + lane < end) ? g_srcs[e0 + lane] : 0;
        for (int j = 0; j < m; j++) {
            int sj = __shfl_sync(FULLM, s, j);
            float2 r = __half22float2(t[(size_t)sj * 32 + lane]);
            ax0 += r.x; ay0 += r.y;
        }
    }
    float d = g_dinv[node];
    float2 bv = ((const float2*)b1)[lane];
    float hx = tanhf(d * (ax0 + ax1) + bv.x);   // h1[2*lane]
    float hy = tanhf(d * (ay0 + ay1) + bv.y);   // h1[2*lane+1]

    // GEMM 64->32: lane f computes sum_k h1[k]*W2[k,f]
    float acc = 0.f;
#pragma unroll
    for (int k = 0; k < 32; k++) {
        float x0 = __shfl_sync(FULLM, hx, k);
        float x1 = __shfl_sync(FULLM, hy, k);
        acc += x0 * sW[(2 * k) * 32 + lane] + x1 * sW[(2 * k + 1) * 32 + lane];
    }
    g_H2[(size_t)node * 32 + lane] = __float2half(acc * d);
}

// ---------------- F2: aggregate 32d + tanh + GEMM 32->16 -> H3 ------------------
__global__ __launch_bounds__(256) void k_f2(
    const float* __restrict__ b2, const float* __restrict__ W3)
{
    __shared__ float sW[32 * 16];
    for (int i = threadIdx.x; i < 32 * 16; i += blockDim.x) sW[i] = W3[i];
    __syncthreads();

    int warp = (blockIdx.x * blockDim.x + threadIdx.x) >> 5;
    int lane = threadIdx.x & 31;
    if (warp >= N_NODES) return;
    const int node = warp;
    const __half2* t = (const __half2*)g_H2;
    int sub = lane >> 4;
    int c   = lane & 15;

    float ax = 0.f, ay = 0.f, bx = 0.f, by = 0.f;
    if (sub == 0) {
        float2 s = __half22float2(t[(size_t)node * 16 + c]);
        ax = s.x; ay = s.y;
    }
    int start = g_rowptr[node];
    int end   = g_rowptr[node + 1];
    int e = start + sub;
    for (; e + 14 < end; e += 16) {      // 8-way unroll (stride 2)
        int s0 = g_srcs[e];
        int s1 = g_srcs[e + 2];
        int s2 = g_srcs[e + 4];
        int s3 = g_srcs[e + 6];
        int s4 = g_srcs[e + 8];
        int s5 = g_srcs[e + 10];
        int s6 = g_srcs[e + 12];
        int s7 = g_srcs[e + 14];
        float2 r0 = __half22float2(t[(size_t)s0 * 16 + c]);
        float2 r1 = __half22float2(t[(size_t)s1 * 16 + c]);
        float2 r2 = __half22float2(t[(size_t)s2 * 16 + c]);
        float2 r3 = __half22float2(t[(size_t)s3 * 16 + c]);
        float2 r4 = __half22float2(t[(size_t)s4 * 16 + c]);
        float2 r5 = __half22float2(t[(size_t)s5 * 16 + c]);
        float2 r6 = __half22float2(t[(size_t)s6 * 16 + c]);
        float2 r7 = __half22float2(t[(size_t)s7 * 16 + c]);
        ax += r0.x; ay += r0.y;  bx += r1.x; by += r1.y;
        ax += r2.x; ay += r2.y;  bx += r3.x; by += r3.y;
        ax += r4.x; ay += r4.y;  bx += r5.x; by += r5.y;
        ax += r6.x; ay += r6.y;  bx += r7.x; by += r7.y;
    }
    for (; e < end; e += 2) {
        float2 r = __half22float2(t[(size_t)g_srcs[e] * 16 + c]);
        ax += r.x; ay += r.y;
    }
    ax += bx; ay += by;
    ax += __shfl_xor_sync(FULLM, ax, 16);
    ay += __shfl_xor_sync(FULLM, ay, 16);

    float d = g_dinv[node];
    float2 bv = ((const float2*)b2)[c];
    float hx = tanhf(d * ax + bv.x);    // h2[2c]
    float hy = tanhf(d * ay + bv.y);    // h2[2c+1]

    // GEMM 32->16: lanes 0..15 compute f = c
    float acc = 0.f;
#pragma unroll
    for (int k = 0; k < 16; k++) {
        float x0 = __shfl_sync(FULLM, hx, k);
        float x1 = __shfl_sync(FULLM, hy, k);
        acc += x0 * sW[(2 * k) * 16 + c] + x1 * sW[(2 * k + 1) * 16 + c];
    }
    if (sub == 0)
        g_H3[(size_t)node * 16 + c] = __float2half(acc * d);
}

// ---------------- F3: aggregate 16d + tanh + GEMM 16->8 -> H4 (fp32) ------------
__global__ __launch_bounds__(256) void k_f3(
    const float* __restrict__ b3, const float* __restrict__ W4)
{
    __shared__ float sW[16 * 8];
    for (int i = threadIdx.x; i < 16 * 8; i += blockDim.x) sW[i] = W4[i];
    __syncthreads();

    int warp = (blockIdx.x * blockDim.x + threadIdx.x) >> 5;
    int lane = threadIdx.x & 31;
    if (warp >= N_NODES) return;
    const int node = warp;
    const __half2* t = (const __half2*)g_H3;
    int sub = lane >> 3;          // 4 subgroups
    int c   = lane & 7;

    float ax = 0.f, ay = 0.f, bx = 0.f, by = 0.f;
    if (sub == 0) {
        float2 s = __half22float2(t[(size_t)node * 8 + c]);
        ax = s.x; ay = s.y;
    }
    int start = g_rowptr[node];
    int end   = g_rowptr[node + 1];
    int e = start + sub;
    for (; e + 28 < end; e += 32) {     // 8-way: one iter covers 32 edges
        int s0 = g_srcs[e];
        int s1 = g_srcs[e + 4];
        int s2 = g_srcs[e + 8];
        int s3 = g_srcs[e + 12];
        int s4 = g_srcs[e + 16];
        int s5 = g_srcs[e + 20];
        int s6 = g_srcs[e + 24];
        int s7 = g_srcs[e + 28];
        float2 r0 = __half22float2(t[(size_t)s0 * 8 + c]);
        float2 r1 = __half22float2(t[(size_t)s1 * 8 + c]);
        float2 r2 = __half22float2(t[(size_t)s2 * 8 + c]);
        float2 r3 = __half22float2(t[(size_t)s3 * 8 + c]);
        float2 r4 = __half22float2(t[(size_t)s4 * 8 + c]);
        float2 r5 = __half22float2(t[(size_t)s5 * 8 + c]);
        float2 r6 = __half22float2(t[(size_t)s6 * 8 + c]);
        float2 r7 = __half22float2(t[(size_t)s7 * 8 + c]);
        ax += r0.x; ay += r0.y;  bx += r1.x; by += r1.y;
        ax += r2.x; ay += r2.y;  bx += r3.x; by += r3.y;
        ax += r4.x; ay += r4.y;  bx += r5.x; by += r5.y;
        ax += r6.x; ay += r6.y;  bx += r7.x; by += r7.y;
    }
    for (; e < end; e += 4) {
        float2 r = __half22float2(t[(size_t)g_srcs[e] * 8 + c]);
        ax += r.x; ay += r.y;
    }
    ax += bx; ay += by;
    ax += __shfl_xor_sync(FULLM, ax, 8);
    ay += __shfl_xor_sync(FULLM, ay, 8);
    ax += __shfl_xor_sync(FULLM, ax, 16);
    ay += __shfl_xor_sync(FULLM, ay, 16);

    float d = g_dinv[node];
    float2 bv = ((const float2*)b3)[c];
    float hx = tanhf(d * ax + bv.x);    // h3[2c]
    float hy = tanhf(d * ay + bv.y);

    // GEMM 16->8: lanes 0..7 compute f = c
    float acc = 0.f;
#pragma unroll
    for (int k = 0; k < 8; k++) {
        float x0 = __shfl_sync(FULLM, hx, k);
        float x1 = __shfl_sync(FULLM, hy, k);
        acc += x0 * sW[(2 * k) * 8 + c] + x1 * sW[(2 * k + 1) * 8 + c];
    }
    if (sub == 0)
        g_H4[(size_t)node * 8 + c] = acc * d;
}

// ---------------- F4: aggregate 8d (fp32) + tanh + classifier -> d_out ----------
// d_out: [N*2 logits][N*8 hidden]
__global__ __launch_bounds__(256) void k_f4(
    const float* __restrict__ b4, const float* __restrict__ Wc,
    const float* __restrict__ bc, float* __restrict__ dout)
{
    int warp = (blockIdx.x * blockDim.x + threadIdx.x) >> 5;
    int lane = threadIdx.x & 31;
    if (warp >= N_NODES) return;
    const int node = warp;
    const float2* t = (const float2*)g_H4;
    int sub = lane >> 2;          // 8 subgroups
    int c   = lane & 3;

    float ax = 0.f, ay = 0.f, bx = 0.f, by = 0.f;
    if (sub == 0) {
        float2 s = t[(size_t)node * 4 + c];
        ax = s.x; ay = s.y;
    }
    int start = g_rowptr[node];
    int end   = g_rowptr[node + 1];
    int e = start + sub;
    for (; e + 24 < end; e += 32) {
        int s0 = g_srcs[e];
        int s1 = g_srcs[e + 8];
        int s2 = g_srcs[e + 16];
        int s3 = g_srcs[e + 24];
        float2 r0 = t[(size_t)s0 * 4 + c];
        float2 r1 = t[(size_t)s1 * 4 + c];
        float2 r2 = t[(size_t)s2 * 4 + c];
        float2 r3 = t[(size_t)s3 * 4 + c];
        ax += r0.x; ay += r0.y;
        bx += r1.x; by += r1.y;
        ax += r2.x; ay += r2.y;
        bx += r3.x; by += r3.y;
    }
    for (; e < end; e += 8) {
        float2 r = t[(size_t)g_srcs[e] * 4 + c];
        ax += r.x; ay += r.y;
    }
    ax += bx; ay += by;
    ax += __shfl_xor_sync(FULLM, ax, 4);
    ay += __shfl_xor_sync(FULLM, ay, 4);
    ax += __shfl_xor_sync(FULLM, ax, 8);
    ay += __shfl_xor_sync(FULLM, ay, 8);
    ax += __shfl_xor_sync(FULLM, ax, 16);
    ay += __shfl_xor_sync(FULLM, ay, 16);

    float d = g_dinv[node];
    float hx = tanhf(d * ax + b4[2 * c]);      // h4[2c]
    float hy = tanhf(d * ay + b4[2 * c + 1]);  // h4[2c+1]

    // classifier: logits over 8 features (pairs on lanes c=0..3)
    float p0 = hx * Wc[(2 * c) * 2 + 0] + hy * Wc[(2 * c + 1) * 2 + 0];
    float p1 = hx * Wc[(2 * c) * 2 + 1] + hy * Wc[(2 * c + 1) * 2 + 1];
    p0 += __shfl_xor_sync(FULLM, p0, 1);
    p1 += __shfl_xor_sync(FULLM, p1, 1);
    p0 += __shfl_xor_sync(FULLM, p0, 2);
    p1 += __shfl_xor_sync(FULLM, p1, 2);

    if (sub == 0) {
        float2* dh = (float2*)(dout + (size_t)2 * N_NODES);
        dh[(size_t)node * 4 + c] = make_float2(hx, hy);
        if (c == 0) {
            dout[(size_t)node * 2 + 0] = p0 + bc[0];
            dout[(size_t)node * 2 + 1] = p1 + bc[1];
        }
    }
}

// ---------------- launcher --------------------------------------------------------
extern "C" void kernel_launch(void* const* d_in, const int* in_sizes, int n_in,
                              void* d_out, int out_size)
{
    const float* x  = (const float*)d_in[0];
    const void*  ei = d_in[1];
    const float* W1 = (const float*)d_in[2];
    const float* b1 = (const float*)d_in[3];
    const float* W2 = (const float*)d_in[4];
    const float* b2 = (const float*)d_in[5];
    const float* W3 = (const float*)d_in[6];
    const float* b3 = (const float*)d_in[7];
    const float* W4 = (const float*)d_in[8];
    const float* b4 = (const float*)d_in[9];
    const float* Wc = (const float*)d_in[10];
    const float* bc = (const float*)d_in[11];
    float* out = (float*)d_out;

    const int nb = (N_NODES + TB - 1) / TB;
    const int wb = (N_NODES * 32 + TB - 1) / TB;  // one warp per node

    k_init<<<nb, TB>>>(ei);                 // 0
    k_count<<<EB, TB>>>(ei);                // 1
    k_scan<<<SCAN_NBLK, SCAN_B>>>();        // 2  (single-pass lookback scan)
    k_fill_gemm1<<<EB + GB, TB>>>(ei, x, W1); // 3  (profiled launch)
    k_f1<<<wb, TB>>>(b1, W2);               // 4
    k_f2<<<wb, TB>>>(b2, W3);               // 5
    k_f3<<<wb, TB>>>(b3, W4);               // 6
    k_f4<<<wb, TB>>>(b4, Wc, bc, out);      // 7
}

// round 10
// speedup vs baseline: 1.0790x; 1.0790x over previous
#include <cuda_runtime.h>
#include <cuda_fp16.h>
#include <math.h>

#define N_NODES 100000
#define N_EDGES 3200000
#define SCAN_B  512
#define SCAN_NBLK ((N_NODES + SCAN_B - 1) / SCAN_B)   // 196
#define FULLM 0xffffffffu
#define TB 256
#define EB ((N_EDGES + TB - 1) / TB)                  // fill blocks (12500)
#define G1B ((N_NODES + 7) / 8)                       // gemm1 warp blocks (12500)

// ---------------- device scratch ----------------------------------------------
__device__ int    g_is64;
__device__ int    g_cnt[N_NODES];
__device__ int    g_rowptr[N_NODES + 1];
__device__ int    g_rank[N_EDGES];       // per-edge rank within dst bucket
__device__ int    g_srcs[N_EDGES];
__device__ unsigned long long g_scan_pack[SCAN_NBLK]; // (value<<2)|flag: 1=agg,2=incl
__device__ float  g_dinv[N_NODES];
__device__ __half g_H1[N_NODES * 64];   // layer-1 gather buf (128B rows)
__device__ __half g_H2[N_NODES * 32];   // layer-2 gather buf (64B rows)
__device__ __half g_H3[N_NODES * 16];   // layer-3 gather buf (32B rows)
__device__ float  g_H4[N_NODES * 8];    // layer-4 gather buf (32B rows, fp32)

// ---------------- init: zero cnt + scan state + dtype detect --------------------
__global__ __launch_bounds__(TB) void k_init(const void* ei) {
    int i = blockIdx.x * blockDim.x + threadIdx.x;
    if (i < N_NODES) g_cnt[i] = 0;
    if (blockIdx.x == 0) {
        __shared__ int any_nz;
        if (threadIdx.x == 0) any_nz = 0;
        __syncthreads();
        const int* w = (const int*)ei;
        for (int k = threadIdx.x; k < 4096; k += blockDim.x)
            if (w[2 * k + 1] != 0) any_nz = 1;
        __syncthreads();
        if (threadIdx.x == 0) g_is64 = any_nz ? 0 : 1;
    }
    if (blockIdx.x == 1 && threadIdx.x < SCAN_NBLK)
        g_scan_pack[threadIdx.x] = 0ull;
}

// ---------------- CSR count + per-edge rank --------------------------------------
__global__ void k_count(const void* __restrict__ ei) {
    int e = blockIdx.x * blockDim.x + threadIdx.x;
    if (e < N_EDGES) {
        int d = g_is64 ? (int)((const long long*)ei)[(long long)N_EDGES + e]
                       : ((const int*)ei)[N_EDGES + e];
        int r = 0;
        if ((unsigned)d < N_NODES) r = atomicAdd(&g_cnt[d], 1);
        g_rank[e] = r;
    }
}

// ---------------- single-pass scan (decoupled lookback) + finalize ---------------
__global__ __launch_bounds__(SCAN_B) void k_scan() {
    __shared__ int wsum[SCAN_B / 32];
    __shared__ int s_total;
    __shared__ int s_base;
    int tid  = threadIdx.x;
    int lane = tid & 31;
    int wid  = tid >> 5;
    int b    = blockIdx.x;
    int idx  = b * SCAN_B + tid;
    int v = (idx < N_NODES) ? g_cnt[idx] : 0;

    int incl = v;
#pragma unroll
    for (int off = 1; off < 32; off <<= 1) {
        int t = __shfl_up_sync(FULLM, incl, off);
        if (lane >= off) incl += t;
    }
    if (lane == 31) wsum[wid] = incl;
    __syncthreads();
    if (wid == 0) {
        int ws = (lane < SCAN_B / 32) ? wsum[lane] : 0;
#pragma unroll
        for (int off = 1; off < SCAN_B / 32; off <<= 1) {
            int t = __shfl_up_sync(FULLM, ws, off);
            if (lane >= off) ws += t;
        }
        if (lane < SCAN_B / 32) wsum[lane] = ws;
    }
    __syncthreads();
    int base = (wid > 0) ? wsum[wid - 1] : 0;
    int excl = base + incl - v;
    if (tid == SCAN_B - 1) s_total = base + incl;
    __syncthreads();

    // decoupled lookback (all 196 blocks co-resident -> no deadlock)
    if (tid == 0) {
        int total = s_total;
        if (b == 0) {
            atomicExch(&g_scan_pack[0], ((unsigned long long)total << 2) | 2ull);
            s_base = 0;
        } else {
            atomicExch(&g_scan_pack[b], ((unsigned long long)total << 2) | 1ull);
            int run = 0;
            int i = b - 1;
            while (true) {
                unsigned long long p;
                do { p = atomicAdd(&g_scan_pack[i], 0ull); } while ((p & 3ull) == 0ull);
                run += (int)(p >> 2);
                if ((p & 3ull) == 2ull) break;
                i--;
            }
            atomicExch(&g_scan_pack[b],
                       ((unsigned long long)(run + total) << 2) | 2ull);
            s_base = run;
        }
    }
    __syncthreads();

    if (idx < N_NODES) {
        int rp = s_base + excl;
        g_rowptr[idx] = rp;
        g_dinv[idx]   = rsqrtf((float)v + 1.0f);   // +1 self loop
    }
    if (b == SCAN_NBLK - 1 && tid == 0)
        g_rowptr[N_NODES] = s_base + s_total;
}

// ---------------- fused: atomic-free CSR fill + warp-per-node gemm1 --------------
// blocks [0, EB): srcs[rowptr[d]+rank[e]] = s
// blocks [EB, EB+G1B): warp per node, H1 = half((x @ W1)*dinv)
__global__ __launch_bounds__(TB) void k_fill_gemm1(
    const void* __restrict__ ei, const float* __restrict__ x,
    const float* __restrict__ W)
{
    __shared__ float2 sW2[34 * 32];   // W1 as float2 pairs: sW2[k*32+j] = W[k][2j..2j+1]
    if (blockIdx.x < EB) {
        int e = blockIdx.x * TB + threadIdx.x;
        if (e < N_EDGES) {
            int is64 = g_is64;
            int s, d;
            if (is64) {
                s = (int)((const long long*)ei)[e];
                d = (int)((const long long*)ei)[(long long)N_EDGES + e];
            } else {
                s = ((const int*)ei)[e];
                d = ((const int*)ei)[N_EDGES + e];
            }
            if ((unsigned)d < N_NODES)
                g_srcs[g_rowptr[d] + g_rank[e]] = s;
        }
    } else {
        for (int i = threadIdx.x; i < 34 * 32; i += blockDim.x) {
            int k = i >> 5, j = i & 31;
            sW2[i] = make_float2(W[k * 64 + 2 * j], W[k * 64 + 2 * j + 1]);
        }
        __syncthreads();
        int warp = (blockIdx.x - EB) * 8 + (threadIdx.x >> 5);
        int lane = threadIdx.x & 31;
        if (warp >= N_NODES) return;
        const int node = warp;

        // lane c<17 loads x-row float2 (rows are 136B = 8B-aligned)
        const float2* xr = (const float2*)(x + (size_t)node * 34);
        float2 xv = (lane < 17) ? xr[lane] : make_float2(0.f, 0.f);

        float a0 = 0.f, a1 = 0.f;
#pragma unroll
        for (int k = 0; k < 17; k++) {
            float x0 = __shfl_sync(FULLM, xv.x, k);
            float x1 = __shfl_sync(FULLM, xv.y, k);
            float2 w0 = sW2[(2 * k) * 32 + lane];
            float2 w1 = sW2[(2 * k + 1) * 32 + lane];
            a0 += x0 * w0.x + x1 * w1.x;
            a1 += x0 * w0.y + x1 * w1.y;
        }
        float d = g_dinv[node];
        ((__half2*)g_H1)[(size_t)node * 32 + lane] =
            __floats2half2_rn(a0 * d, a1 * d);
    }
}

// ---------------- F1: aggregate 64d + tanh + GEMM 64->32 -> H2 ------------------
__global__ __launch_bounds__(256) void k_f1(
    const float* __restrict__ b1, const float* __restrict__ W2)
{
    __shared__ float sW[64 * 32];   // 8KB
    for (int i = threadIdx.x; i < 64 * 32; i += blockDim.x) sW[i] = W2[i];
    __syncthreads();

    int warp = (blockIdx.x * blockDim.x + threadIdx.x) >> 5;
    int lane = threadIdx.x & 31;
    if (warp >= N_NODES) return;
    const int node = warp;
    const __half2* t = (const __half2*)g_H1;

    float2 self = __half22float2(t[(size_t)node * 32 + lane]);
    float ax0 = self.x, ay0 = self.y, ax1 = 0.f, ay1 = 0.f;

    int start = g_rowptr[node];
    int end   = g_rowptr[node + 1];
    int e0 = start;
    for (; e0 + 32 <= end; e0 += 32) {
        int s = g_srcs[e0 + lane];
#pragma unroll
        for (int j = 0; j < 32; j += 2) {
            int s0 = __shfl_sync(FULLM, s, j);
            int s1 = __shfl_sync(FULLM, s, j + 1);
            float2 r0 = __half22float2(t[(size_t)s0 * 32 + lane]);
            float2 r1 = __half22float2(t[(size_t)s1 * 32 + lane]);
            ax0 += r0.x; ay0 += r0.y;
            ax1 += r1.x; ay1 += r1.y;
        }
    }
    if (e0 < end) {
        int m = end - e0;
        int s = (e0 + lane < end) ? g_srcs[e0 + lane] : 0;
        for (int j = 0; j < m; j++) {
            int sj = __shfl_sync(FULLM, s, j);
            float2 r = __half22float2(t[(size_t)sj * 32 + lane]);
            ax0 += r.x; ay0 += r.y;
        }
    }
    float d = g_dinv[node];
    float2 bv = ((const float2*)b1)[lane];
    float hx = tanhf(d * (ax0 + ax1) + bv.x);   // h1[2*lane]
    float hy = tanhf(d * (ay0 + ay1) + bv.y);   // h1[2*lane+1]

    // GEMM 64->32: lane f computes sum_k h1[k]*W2[k,f]
    float acc = 0.f;
#pragma unroll
    for (int k = 0; k < 32; k++) {
        float x0 = __shfl_sync(FULLM, hx, k);
        float x1 = __shfl_sync(FULLM, hy, k);
        acc += x0 * sW[(2 * k) * 32 + lane] + x1 * sW[(2 * k + 1) * 32 + lane];
    }
    g_H2[(size_t)node * 32 + lane] = __float2half(acc * d);
}

// ---------------- F2: aggregate 32d + tanh + GEMM 32->16 -> H3 ------------------
__global__ __launch_bounds__(256) void k_f2(
    const float* __restrict__ b2, const float* __restrict__ W3)
{
    __shared__ float sW[32 * 16];
    for (int i = threadIdx.x; i < 32 * 16; i += blockDim.x) sW[i] = W3[i];
    __syncthreads();

    int warp = (blockIdx.x * blockDim.x + threadIdx.x) >> 5;
    int lane = threadIdx.x & 31;
    if (warp >= N_NODES) return;
    const int node = warp;
    const __half2* t = (const __half2*)g_H2;
    int sub = lane >> 4;
    int c   = lane & 15;

    float ax = 0.f, ay = 0.f, bx = 0.f, by = 0.f;
    if (sub == 0) {
        float2 s = __half22float2(t[(size_t)node * 16 + c]);
        ax = s.x; ay = s.y;
    }
    int start = g_rowptr[node];
    int end   = g_rowptr[node + 1];
    int e = start + sub;
    for (; e + 14 < end; e += 16) {      // 8-way unroll (stride 2)
        int s0 = g_srcs[e];
        int s1 = g_srcs[e + 2];
        int s2 = g_srcs[e + 4];
        int s3 = g_srcs[e + 6];
        int s4 = g_srcs[e + 8];
        int s5 = g_srcs[e + 10];
        int s6 = g_srcs[e + 12];
        int s7 = g_srcs[e + 14];
        float2 r0 = __half22float2(t[(size_t)s0 * 16 + c]);
        float2 r1 = __half22float2(t[(size_t)s1 * 16 + c]);
        float2 r2 = __half22float2(t[(size_t)s2 * 16 + c]);
        float2 r3 = __half22float2(t[(size_t)s3 * 16 + c]);
        float2 r4 = __half22float2(t[(size_t)s4 * 16 + c]);
        float2 r5 = __half22float2(t[(size_t)s5 * 16 + c]);
        float2 r6 = __half22float2(t[(size_t)s6 * 16 + c]);
        float2 r7 = __half22float2(t[(size_t)s7 * 16 + c]);
        ax += r0.x; ay += r0.y;  bx += r1.x; by += r1.y;
        ax += r2.x; ay += r2.y;  bx += r3.x; by += r3.y;
        ax += r4.x; ay += r4.y;  bx += r5.x; by += r5.y;
        ax += r6.x; ay += r6.y;  bx += r7.x; by += r7.y;
    }
    for (; e < end; e += 2) {
        float2 r = __half22float2(t[(size_t)g_srcs[e] * 16 + c]);
        ax += r.x; ay += r.y;
    }
    ax += bx; ay += by;
    ax += __shfl_xor_sync(FULLM, ax, 16);
    ay += __shfl_xor_sync(FULLM, ay, 16);

    float d = g_dinv[node];
    float2 bv = ((const float2*)b2)[c];
    float hx = tanhf(d * ax + bv.x);    // h2[2c]
    float hy = tanhf(d * ay + bv.y);    // h2[2c+1]

    // GEMM 32->16: lanes 0..15 compute f = c
    float acc = 0.f;
#pragma unroll
    for (int k = 0; k < 16; k++) {
        float x0 = __shfl_sync(FULLM, hx, k);
        float x1 = __shfl_sync(FULLM, hy, k);
        acc += x0 * sW[(2 * k) * 16 + c] + x1 * sW[(2 * k + 1) * 16 + c];
    }
    if (sub == 0)
        g_H3[(size_t)node * 16 + c] = __float2half(acc * d);
}

// ---------------- F3: aggregate 16d + tanh + GEMM 16->8 -> H4 (fp32) ------------
__global__ __launch_bounds__(256) void k_f3(
    const float* __restrict__ b3, const float* __restrict__ W4)
{
    __shared__ float sW[16 * 8];
    for (int i = threadIdx.x; i < 16 * 8; i += blockDim.x) sW[i] = W4[i];
    __syncthreads();

    int warp = (blockIdx.x * blockDim.x + threadIdx.x) >> 5;
    int lane = threadIdx.x & 31;
    if (warp >= N_NODES) return;
    const int node = warp;
    const __half2* t = (const __half2*)g_H3;
    int sub = lane >> 3;          // 4 subgroups
    int c   = lane & 7;

    float ax = 0.f, ay = 0.f, bx = 0.f, by = 0.f;
    if (sub == 0) {
        float2 s = __half22float2(t[(size_t)node * 8 + c]);
        ax = s.x; ay = s.y;
    }
    int start = g_rowptr[node];
    int end   = g_rowptr[node + 1];
    int e = start + sub;
    for (; e + 28 < end; e += 32) {     // 8-way: one iter covers 32 edges
        int s0 = g_srcs[e];
        int s1 = g_srcs[e + 4];
        int s2 = g_srcs[e + 8];
        int s3 = g_srcs[e + 12];
        int s4 = g_srcs[e + 16];
        int s5 = g_srcs[e + 20];
        int s6 = g_srcs[e + 24];
        int s7 = g_srcs[e + 28];
        float2 r0 = __half22float2(t[(size_t)s0 * 8 + c]);
        float2 r1 = __half22float2(t[(size_t)s1 * 8 + c]);
        float2 r2 = __half22float2(t[(size_t)s2 * 8 + c]);
        float2 r3 = __half22float2(t[(size_t)s3 * 8 + c]);
        float2 r4 = __half22float2(t[(size_t)s4 * 8 + c]);
        float2 r5 = __half22float2(t[(size_t)s5 * 8 + c]);
        float2 r6 = __half22float2(t[(size_t)s6 * 8 + c]);
        float2 r7 = __half22float2(t[(size_t)s7 * 8 + c]);
        ax += r0.x; ay += r0.y;  bx += r1.x; by += r1.y;
        ax += r2.x; ay += r2.y;  bx += r3.x; by += r3.y;
        ax += r4.x; ay += r4.y;  bx += r5.x; by += r5.y;
        ax += r6.x; ay += r6.y;  bx += r7.x; by += r7.y;
    }
    for (; e < end; e += 4) {
        float2 r = __half22float2(t[(size_t)g_srcs[e] * 8 + c]);
        ax += r.x; ay += r.y;
    }
    ax += bx; ay += by;
    ax += __shfl_xor_sync(FULLM, ax, 8);
    ay += __shfl_xor_sync(FULLM, ay, 8);
    ax += __shfl_xor_sync(FULLM, ax, 16);
    ay += __shfl_xor_sync(FULLM, ay, 16);

    float d = g_dinv[node];
    float2 bv = ((const float2*)b3)[c];
    float hx = tanhf(d * ax + bv.x);    // h3[2c]
    float hy = tanhf(d * ay + bv.y);

    // GEMM 16->8: lanes 0..7 compute f = c
    float acc = 0.f;
#pragma unroll
    for (int k = 0; k < 8; k++) {
        float x0 = __shfl_sync(FULLM, hx, k);
        float x1 = __shfl_sync(FULLM, hy, k);
        acc += x0 * sW[(2 * k) * 8 + c] + x1 * sW[(2 * k + 1) * 8 + c];
    }
    if (sub == 0)
        g_H4[(size_t)node * 8 + c] = acc * d;
}

// ---------------- F4: aggregate 8d (fp32) + tanh + classifier -> d_out ----------
// d_out: [N*2 logits][N*8 hidden]
__global__ __launch_bounds__(256) void k_f4(
    const float* __restrict__ b4, const float* __restrict__ Wc,
    const float* __restrict__ bc, float* __restrict__ dout)
{
    int warp = (blockIdx.x * blockDim.x + threadIdx.x) >> 5;
    int lane = threadIdx.x & 31;
    if (warp >= N_NODES) return;
    const int node = warp;
    const float2* t = (const float2*)g_H4;
    int sub = lane >> 2;          // 8 subgroups
    int c   = lane & 3;

    float ax = 0.f, ay = 0.f, bx = 0.f, by = 0.f;
    if (sub == 0) {
        float2 s = t[(size_t)node * 4 + c];
        ax = s.x; ay = s.y;
    }
    int start = g_rowptr[node];
    int end   = g_rowptr[node + 1];
    int e = start + sub;
    for (; e + 24 < end; e += 32) {
        int s0 = g_srcs[e];
        int s1 = g_srcs[e + 8];
        int s2 = g_srcs[e + 16];
        int s3 = g_srcs[e + 24];
        float2 r0 = t[(size_t)s0 * 4 + c];
        float2 r1 = t[(size_t)s1 * 4 + c];
        float2 r2 = t[(size_t)s2 * 4 + c];
        float2 r3 = t[(size_t)s3 * 4 + c];
        ax += r0.x; ay += r0.y;
        bx += r1.x; by += r1.y;
        ax += r2.x; ay += r2.y;
        bx += r3.x; by += r3.y;
    }
    for (; e < end; e += 8) {
        float2 r = t[(size_t)g_srcs[e] * 4 + c];
        ax += r.x; ay += r.y;
    }
    ax += bx; ay += by;
    ax += __shfl_xor_sync(FULLM, ax, 4);
    ay += __shfl_xor_sync(FULLM, ay, 4);
    ax += __shfl_xor_sync(FULLM, ax, 8);
    ay += __shfl_xor_sync(FULLM, ay, 8);
    ax += __shfl_xor_sync(FULLM, ax, 16);
    ay += __shfl_xor_sync(FULLM, ay, 16);

    float d = g_dinv[node];
    float hx = tanhf(d * ax + b4[2 * c]);      // h4[2c]
    float hy = tanhf(d * ay + b4[2 * c + 1]);  // h4[2c+1]

    // classifier: logits over 8 features (pairs on lanes c=0..3)
    float p0 = hx * Wc[(2 * c) * 2 + 0] + hy * Wc[(2 * c + 1) * 2 + 0];
    float p1 = hx * Wc[(2 * c) * 2 + 1] + hy * Wc[(2 * c + 1) * 2 + 1];
    p0 += __shfl_xor_sync(FULLM, p0, 1);
    p1 += __shfl_xor_sync(FULLM, p1, 1);
    p0 += __shfl_xor_sync(FULLM, p0, 2);
    p1 += __shfl_xor_sync(FULLM, p1, 2);

    if (sub == 0) {
        float2* dh = (float2*)(dout + (size_t)2 * N_NODES);
        dh[(size_t)node * 4 + c] = make_float2(hx, hy);
        if (c == 0) {
            dout[(size_t)node * 2 + 0] = p0 + bc[0];
            dout[(size_t)node * 2 + 1] = p1 + bc[1];
        }
    }
}

// ---------------- launcher --------------------------------------------------------
extern "C" void kernel_launch(void* const* d_in, const int* in_sizes, int n_in,
                              void* d_out, int out_size)
{
    const float* x  = (const float*)d_in[0];
    const void*  ei = d_in[1];
    const float* W1 = (const float*)d_in[2];
    const float* b1 = (const float*)d_in[3];
    const float* W2 = (const float*)d_in[4];
    const float* b2 = (const float*)d_in[5];
    const float* W3 = (const float*)d_in[6];
    const float* b3 = (const float*)d_in[7];
    const float* W4 = (const float*)d_in[8];
    const float* b4 = (const float*)d_in[9];
    const float* Wc = (const float*)d_in[10];
    const float* bc = (const float*)d_in[11];
    float* out = (float*)d_out;

    const int nb = (N_NODES + TB - 1) / TB;
    const int wb = (N_NODES * 32 + TB - 1) / TB;  // one warp per node

    k_init<<<nb, TB>>>(ei);                    // 0
    k_count<<<EB, TB>>>(ei);                   // 1  (atomics + rank store)
    k_scan<<<SCAN_NBLK, SCAN_B>>>();           // 2  (single-pass lookback scan)
    k_fill_gemm1<<<EB + G1B, TB>>>(ei, x, W1); // 3  (profiled: atomic-free fill + warp gemm1)
    k_f1<<<wb, TB>>>(b1, W2);                  // 4
    k_f2<<<wb, TB>>>(b2, W3);                  // 5
    k_f3<<<wb, TB>>>(b3, W4);                  // 6
    k_f4<<<wb, TB>>>(b4, Wc, bc, out);         // 7
}

// round 11
// speedup vs baseline: 1.1622x; 1.0772x over previous
#include <cuda_runtime.h>
#include <cuda_fp16.h>
#include <math.h>

#define N_NODES 100000
#define N_EDGES 3200000
#define FULLM 0xffffffffu
#define TB 256
#define EB ((N_EDGES + TB - 1) / TB)                  // edge blocks (12500)
#define G1B ((N_NODES + 7) / 8)                       // gemm1 warp blocks (12500)
#define CAP 64                                        // bin slots per node
#define OVF_CAP 32768

// ---------------- device scratch ----------------------------------------------
__device__ int    g_is64;
__device__ int    g_cnt[N_NODES];
__device__ int    g_bins[N_NODES * CAP];  // src ids, bins[d*64 + r]
__device__ int    g_ovf_cnt;
__device__ int    g_ovf_d[OVF_CAP];
__device__ int    g_ovf_s[OVF_CAP];
__device__ float  g_dinv[N_NODES];
__device__ __half g_H1[N_NODES * 64];   // layer-1 gather buf (128B rows)
__device__ __half g_H2[N_NODES * 32];   // layer-2 gather buf (64B rows)
__device__ __half g_H3[N_NODES * 16];   // layer-3 gather buf (32B rows)
__device__ float  g_H4[N_NODES * 8];    // layer-4 gather buf (32B rows, fp32)

// ---------------- init: zero cnt + ovf + dtype detect ---------------------------
__global__ __launch_bounds__(TB) void k_init(const void* ei) {
    int i = blockIdx.x * blockDim.x + threadIdx.x;
    if (i < N_NODES) g_cnt[i] = 0;
    if (blockIdx.x == 0) {
        __shared__ int any_nz;
        if (threadIdx.x == 0) { any_nz = 0; g_ovf_cnt = 0; }
        __syncthreads();
        const int* w = (const int*)ei;
        for (int k = threadIdx.x; k < 4096; k += blockDim.x)
            if (w[2 * k + 1] != 0) any_nz = 1;
        __syncthreads();
        if (threadIdx.x == 0) g_is64 = any_nz ? 0 : 1;
    }
}

// ---------------- count + direct bin fill ----------------------------------------
__global__ void k_count_fill(const void* __restrict__ ei) {
    int e = blockIdx.x * blockDim.x + threadIdx.x;
    if (e < N_EDGES) {
        int is64 = g_is64;
        int s, d;
        if (is64) {
            s = (int)((const long long*)ei)[e];
            d = (int)((const long long*)ei)[(long long)N_EDGES + e];
        } else {
            s = ((const int*)ei)[e];
            d = ((const int*)ei)[N_EDGES + e];
        }
        if ((unsigned)d < N_NODES) {
            int r = atomicAdd(&g_cnt[d], 1);
            if (r < CAP) {
                g_bins[d * CAP + r] = s;
            } else {
                int o = atomicAdd(&g_ovf_cnt, 1);
                if (o < OVF_CAP) { g_ovf_d[o] = d; g_ovf_s[o] = s; }
            }
        }
    }
}

// ---------------- gemm1 (warp per node) + dinv ------------------------------------
__global__ __launch_bounds__(TB) void k_gemm1(
    const float* __restrict__ x, const float* __restrict__ W)
{
    __shared__ float2 sW2[34 * 32];   // sW2[k*32+j] = W[k][2j..2j+1]
    for (int i = threadIdx.x; i < 34 * 32; i += blockDim.x) {
        int k = i >> 5, j = i & 31;
        sW2[i] = make_float2(W[k * 64 + 2 * j], W[k * 64 + 2 * j + 1]);
    }
    __syncthreads();
    int warp = blockIdx.x * 8 + (threadIdx.x >> 5);
    int lane = threadIdx.x & 31;
    if (warp >= N_NODES) return;
    const int node = warp;

    const float2* xr = (const float2*)(x + (size_t)node * 34);
    float2 xv = (lane < 17) ? xr[lane] : make_float2(0.f, 0.f);

    float a0 = 0.f, a1 = 0.f;
#pragma unroll
    for (int k = 0; k < 17; k++) {
        float x0 = __shfl_sync(FULLM, xv.x, k);
        float x1 = __shfl_sync(FULLM, xv.y, k);
        float2 w0 = sW2[(2 * k) * 32 + lane];
        float2 w1 = sW2[(2 * k + 1) * 32 + lane];
        a0 += x0 * w0.x + x1 * w1.x;
        a1 += x0 * w0.y + x1 * w1.y;
    }
    float dv = rsqrtf((float)g_cnt[node] + 1.0f);   // +1 self loop
    if (lane == 0) g_dinv[node] = dv;
    ((__half2*)g_H1)[(size_t)node * 32 + lane] =
        __floats2half2_rn(a0 * dv, a1 * dv);
}

// ---------------- F1: aggregate 64d + tanh + GEMM 64->32 -> H2 ------------------
__global__ __launch_bounds__(256) void k_f1(
    const float* __restrict__ b1, const float* __restrict__ W2)
{
    __shared__ float sW[64 * 32];   // 8KB
    for (int i = threadIdx.x; i < 64 * 32; i += blockDim.x) sW[i] = W2[i];
    __syncthreads();

    int warp = (blockIdx.x * blockDim.x + threadIdx.x) >> 5;
    int lane = threadIdx.x & 31;
    if (warp >= N_NODES) return;
    const int node = warp;
    const __half2* t = (const __half2*)g_H1;

    float2 self = __half22float2(t[(size_t)node * 32 + lane]);
    float ax0 = self.x, ay0 = self.y, ax1 = 0.f, ay1 = 0.f;

    int deg = g_cnt[node];
    int m = min(deg, CAP);
    const int* bin = g_bins + node * CAP;
    int e0 = 0;
    for (; e0 + 32 <= m; e0 += 32) {
        int s = bin[e0 + lane];
#pragma unroll
        for (int j = 0; j < 32; j += 2) {
            int s0 = __shfl_sync(FULLM, s, j);
            int s1 = __shfl_sync(FULLM, s, j + 1);
            float2 r0 = __half22float2(t[(size_t)s0 * 32 + lane]);
            float2 r1 = __half22float2(t[(size_t)s1 * 32 + lane]);
            ax0 += r0.x; ay0 += r0.y;
            ax1 += r1.x; ay1 += r1.y;
        }
    }
    if (e0 < m) {
        int mm = m - e0;
        int s = (e0 + lane < m) ? bin[e0 + lane] : 0;
        for (int j = 0; j < mm; j++) {
            int sj = __shfl_sync(FULLM, s, j);
            float2 r = __half22float2(t[(size_t)sj * 32 + lane]);
            ax0 += r.x; ay0 += r.y;
        }
    }
    // overflow edges (normally none)
    int L = g_ovf_cnt; if (L > OVF_CAP) L = OVF_CAP;
    for (int i = 0; i < L; i++) {
        if (g_ovf_d[i] == node) {
            float2 r = __half22float2(t[(size_t)g_ovf_s[i] * 32 + lane]);
            ax0 += r.x; ay0 += r.y;
        }
    }

    float d = g_dinv[node];
    float2 bv = ((const float2*)b1)[lane];
    float hx = tanhf(d * (ax0 + ax1) + bv.x);   // h1[2*lane]
    float hy = tanhf(d * (ay0 + ay1) + bv.y);   // h1[2*lane+1]

    // GEMM 64->32
    float acc = 0.f;
#pragma unroll
    for (int k = 0; k < 32; k++) {
        float x0 = __shfl_sync(FULLM, hx, k);
        float x1 = __shfl_sync(FULLM, hy, k);
        acc += x0 * sW[(2 * k) * 32 + lane] + x1 * sW[(2 * k + 1) * 32 + lane];
    }
    g_H2[(size_t)node * 32 + lane] = __float2half(acc * d);
}

// ---------------- F2: aggregate 32d + tanh + GEMM 32->16 -> H3 ------------------
__global__ __launch_bounds__(256) void k_f2(
    const float* __restrict__ b2, const float* __restrict__ W3)
{
    __shared__ float sW[32 * 16];
    for (int i = threadIdx.x; i < 32 * 16; i += blockDim.x) sW[i] = W3[i];
    __syncthreads();

    int warp = (blockIdx.x * blockDim.x + threadIdx.x) >> 5;
    int lane = threadIdx.x & 31;
    if (warp >= N_NODES) return;
    const int node = warp;
    const __half2* t = (const __half2*)g_H2;
    int sub = lane >> 4;          // 2 subgroups
    int c   = lane & 15;

    float ax = 0.f, ay = 0.f, bx = 0.f, by = 0.f;
    if (sub == 0) {
        float2 s = __half22float2(t[(size_t)node * 16 + c]);
        ax = s.x; ay = s.y;
    }
    int deg = g_cnt[node];
    int m = min(deg, CAP);
    const int* bin = g_bins + node * CAP;
    int e = sub;
    for (; e + 14 < m; e += 16) {
        int s0 = bin[e];
        int s1 = bin[e + 2];
        int s2 = bin[e + 4];
        int s3 = bin[e + 6];
        int s4 = bin[e + 8];
        int s5 = bin[e + 10];
        int s6 = bin[e + 12];
        int s7 = bin[e + 14];
        float2 r0 = __half22float2(t[(size_t)s0 * 16 + c]);
        float2 r1 = __half22float2(t[(size_t)s1 * 16 + c]);
        float2 r2 = __half22float2(t[(size_t)s2 * 16 + c]);
        float2 r3 = __half22float2(t[(size_t)s3 * 16 + c]);
        float2 r4 = __half22float2(t[(size_t)s4 * 16 + c]);
        float2 r5 = __half22float2(t[(size_t)s5 * 16 + c]);
        float2 r6 = __half22float2(t[(size_t)s6 * 16 + c]);
        float2 r7 = __half22float2(t[(size_t)s7 * 16 + c]);
        ax += r0.x; ay += r0.y;  bx += r1.x; by += r1.y;
        ax += r2.x; ay += r2.y;  bx += r3.x; by += r3.y;
        ax += r4.x; ay += r4.y;  bx += r5.x; by += r5.y;
        ax += r6.x; ay += r6.y;  bx += r7.x; by += r7.y;
    }
    for (; e < m; e += 2) {
        float2 r = __half22float2(t[(size_t)bin[e] * 16 + c]);
        ax += r.x; ay += r.y;
    }
    int L = g_ovf_cnt; if (L > OVF_CAP) L = OVF_CAP;
    for (int i = 0; i < L; i++) {
        if (g_ovf_d[i] == node && (i & 1) == sub) {
            float2 r = __half22float2(t[(size_t)g_ovf_s[i] * 16 + c]);
            ax += r.x; ay += r.y;
        }
    }
    ax += bx; ay += by;
    ax += __shfl_xor_sync(FULLM, ax, 16);
    ay += __shfl_xor_sync(FULLM, ay, 16);

    float d = g_dinv[node];
    float2 bv = ((const float2*)b2)[c];
    float hx = tanhf(d * ax + bv.x);    // h2[2c]
    float hy = tanhf(d * ay + bv.y);    // h2[2c+1]

    // GEMM 32->16
    float acc = 0.f;
#pragma unroll
    for (int k = 0; k < 16; k++) {
        float x0 = __shfl_sync(FULLM, hx, k);
        float x1 = __shfl_sync(FULLM, hy, k);
        acc += x0 * sW[(2 * k) * 16 + c] + x1 * sW[(2 * k + 1) * 16 + c];
    }
    if (sub == 0)
        g_H3[(size_t)node * 16 + c] = __float2half(acc * d);
}

// ---------------- F3: aggregate 16d + tanh + GEMM 16->8 -> H4 (fp32) ------------
__global__ __launch_bounds__(256) void k_f3(
    const float* __restrict__ b3, const float* __restrict__ W4)
{
    __shared__ float sW[16 * 8];
    for (int i = threadIdx.x; i < 16 * 8; i += blockDim.x) sW[i] = W4[i];
    __syncthreads();

    int warp = (blockIdx.x * blockDim.x + threadIdx.x) >> 5;
    int lane = threadIdx.x & 31;
    if (warp >= N_NODES) return;
    const int node = warp;
    const __half2* t = (const __half2*)g_H3;
    int sub = lane >> 3;          // 4 subgroups
    int c   = lane & 7;

    float ax = 0.f, ay = 0.f, bx = 0.f, by = 0.f;
    if (sub == 0) {
        float2 s = __half22float2(t[(size_t)node * 8 + c]);
        ax = s.x; ay = s.y;
    }
    int deg = g_cnt[node];
    int m = min(deg, CAP);
    const int* bin = g_bins + node * CAP;
    int e = sub;
    for (; e + 28 < m; e += 32) {
        int s0 = bin[e];
        int s1 = bin[e + 4];
        int s2 = bin[e + 8];
        int s3 = bin[e + 12];
        int s4 = bin[e + 16];
        int s5 = bin[e + 20];
        int s6 = bin[e + 24];
        int s7 = bin[e + 28];
        float2 r0 = __half22float2(t[(size_t)s0 * 8 + c]);
        float2 r1 = __half22float2(t[(size_t)s1 * 8 + c]);
        float2 r2 = __half22float2(t[(size_t)s2 * 8 + c]);
        float2 r3 = __half22float2(t[(size_t)s3 * 8 + c]);
        float2 r4 = __half22float2(t[(size_t)s4 * 8 + c]);
        float2 r5 = __half22float2(t[(size_t)s5 * 8 + c]);
        float2 r6 = __half22float2(t[(size_t)s6 * 8 + c]);
        float2 r7 = __half22float2(t[(size_t)s7 * 8 + c]);
        ax += r0.x; ay += r0.y;  bx += r1.x; by += r1.y;
        ax += r2.x; ay += r2.y;  bx += r3.x; by += r3.y;
        ax += r4.x; ay += r4.y;  bx += r5.x; by += r5.y;
        ax += r6.x; ay += r6.y;  bx += r7.x; by += r7.y;
    }
    for (; e < m; e += 4) {
        float2 r = __half22float2(t[(size_t)bin[e] * 8 + c]);
        ax += r.x; ay += r.y;
    }
    int L = g_ovf_cnt; if (L > OVF_CAP) L = OVF_CAP;
    for (int i = 0; i < L; i++) {
        if (g_ovf_d[i] == node && (i & 3) == sub) {
            float2 r = __half22float2(t[(size_t)g_ovf_s[i] * 8 + c]);
            ax += r.x; ay += r.y;
        }
    }
    ax += bx; ay += by;
    ax += __shfl_xor_sync(FULLM, ax, 8);
    ay += __shfl_xor_sync(FULLM, ay, 8);
    ax += __shfl_xor_sync(FULLM, ax, 16);
    ay += __shfl_xor_sync(FULLM, ay, 16);

    float d = g_dinv[node];
    float2 bv = ((const float2*)b3)[c];
    float hx = tanhf(d * ax + bv.x);    // h3[2c]
    float hy = tanhf(d * ay + bv.y);

    // GEMM 16->8
    float acc = 0.f;
#pragma unroll
    for (int k = 0; k < 8; k++) {
        float x0 = __shfl_sync(FULLM, hx, k);
        float x1 = __shfl_sync(FULLM, hy, k);
        acc += x0 * sW[(2 * k) * 8 + c] + x1 * sW[(2 * k + 1) * 8 + c];
    }
    if (sub == 0)
        g_H4[(size_t)node * 8 + c] = acc * d;
}

// ---------------- F4: aggregate 8d (fp32) + tanh + classifier -> d_out ----------
// d_out: [N*2 logits][N*8 hidden]
__global__ __launch_bounds__(256) void k_f4(
    const float* __restrict__ b4, const float* __restrict__ Wc,
    const float* __restrict__ bc, float* __restrict__ dout)
{
    int warp = (blockIdx.x * blockDim.x + threadIdx.x) >> 5;
    int lane = threadIdx.x & 31;
    if (warp >= N_NODES) return;
    const int node = warp;
    const float2* t = (const float2*)g_H4;
    int sub = lane >> 2;          // 8 subgroups
    int c   = lane & 3;

    float ax = 0.f, ay = 0.f, bx = 0.f, by = 0.f;
    if (sub == 0) {
        float2 s = t[(size_t)node * 4 + c];
        ax = s.x; ay = s.y;
    }
    int deg = g_cnt[node];
    int m = min(deg, CAP);
    const int* bin = g_bins + node * CAP;
    int e = sub;
    for (; e + 24 < m; e += 32) {
        int s0 = bin[e];
        int s1 = bin[e + 8];
        int s2 = bin[e + 16];
        int s3 = bin[e + 24];
        float2 r0 = t[(size_t)s0 * 4 + c];
        float2 r1 = t[(size_t)s1 * 4 + c];
        float2 r2 = t[(size_t)s2 * 4 + c];
        float2 r3 = t[(size_t)s3 * 4 + c];
        ax += r0.x; ay += r0.y;
        bx += r1.x; by += r1.y;
        ax += r2.x; ay += r2.y;
        bx += r3.x; by += r3.y;
    }
    for (; e < m; e += 8) {
        float2 r = t[(size_t)bin[e] * 4 + c];
        ax += r.x; ay += r.y;
    }
    int L = g_ovf_cnt; if (L > OVF_CAP) L = OVF_CAP;
    for (int i = 0; i < L; i++) {
        if (g_ovf_d[i] == node && (i & 7) == sub) {
            float2 r = t[(size_t)g_ovf_s[i] * 4 + c];
            ax += r.x; ay += r.y;
        }
    }
    ax += bx; ay += by;
    ax += __shfl_xor_sync(FULLM, ax, 4);
    ay += __shfl_xor_sync(FULLM, ay, 4);
    ax += __shfl_xor_sync(FULLM, ax, 8);
    ay += __shfl_xor_sync(FULLM, ay, 8);
    ax += __shfl_xor_sync(FULLM, ax, 16);
    ay += __shfl_xor_sync(FULLM, ay, 16);

    float d = g_dinv[node];
    float hx = tanhf(d * ax + b4[2 * c]);      // h4[2c]
    float hy = tanhf(d * ay + b4[2 * c + 1]);  // h4[2c+1]

    float p0 = hx * Wc[(2 * c) * 2 + 0] + hy * Wc[(2 * c + 1) * 2 + 0];
    float p1 = hx * Wc[(2 * c) * 2 + 1] + hy * Wc[(2 * c + 1) * 2 + 1];
    p0 += __shfl_xor_sync(FULLM, p0, 1);
    p1 += __shfl_xor_sync(FULLM, p1, 1);
    p0 += __shfl_xor_sync(FULLM, p0, 2);
    p1 += __shfl_xor_sync(FULLM, p1, 2);

    if (sub == 0) {
        float2* dh = (float2*)(dout + (size_t)2 * N_NODES);
        dh[(size_t)node * 4 + c] = make_float2(hx, hy);
        if (c == 0) {
            dout[(size_t)node * 2 + 0] = p0 + bc[0];
            dout[(size_t)node * 2 + 1] = p1 + bc[1];
        }
    }
}

// ---------------- launcher --------------------------------------------------------
extern "C" void kernel_launch(void* const* d_in, const int* in_sizes, int n_in,
                              void* d_out, int out_size)
{
    const float* x  = (const float*)d_in[0];
    const void*  ei = d_in[1];
    const float* W1 = (const float*)d_in[2];
    const float* b1 = (const float*)d_in[3];
    const float* W2 = (const float*)d_in[4];
    const float* b2 = (const float*)d_in[5];
    const float* W3 = (const float*)d_in[6];
    const float* b3 = (const float*)d_in[7];
    const float* W4 = (const float*)d_in[8];
    const float* b4 = (const float*)d_in[9];
    const float* Wc = (const float*)d_in[10];
    const float* bc = (const float*)d_in[11];
    float* out = (float*)d_out;

    const int nb = (N_NODES + TB - 1) / TB;
    const int wb = (N_NODES * 32 + TB - 1) / TB;  // one warp per node

    k_init<<<nb, TB>>>(ei);            // 0
    k_count_fill<<<EB, TB>>>(ei);      // 1  (atomic count + direct bin store)
    k_gemm1<<<G1B, TB>>>(x, W1);       // 2  (warp-per-node GEMM + dinv)
    k_f1<<<wb, TB>>>(b1, W2);          // 3  (profiled: dominant 64d gather)
    k_f2<<<wb, TB>>>(b2, W3);          // 4
    k_f3<<<wb, TB>>>(b3, W4);          // 5
    k_f4<<<wb, TB>>>(b4, Wc, bc, out); // 6
}